// round 1
// baseline (speedup 1.0000x reference)
#include <cuda_runtime.h>
#include <math.h>

#define SQ   2048
#define DIM  1024
#define NH   16
#define HD   64
#define DFF  4096
#define NE   8
#define EPSV 1.1920928955078125e-07f
#define NEG_INF (__int_as_float(0xff800000))

// ------------------------- scratch (device globals) -------------------------
__device__ float g_h   [(size_t)SQ*DIM];
__device__ float g_qkv [(size_t)SQ*3*DIM];
__device__ float g_o   [(size_t)SQ*DIM];
__device__ float g_x2  [(size_t)SQ*DIM];
__device__ float g_h2  [(size_t)SQ*DIM];
__device__ float g_probs[(size_t)SQ*NE];
__device__ float g_topw [(size_t)SQ*2];
__device__ int   g_cnt  [NE];
__device__ int   g_atok [(size_t)NE*SQ];
__device__ int   g_aslot[(size_t)NE*SQ];
__device__ float g_hid  [(size_t)NE*SQ*DFF];   // 256 MB bss scratch
__device__ float g_y    [(size_t)SQ*2*DIM];

// ------------------------- small kernels -------------------------
__global__ void zero_cnt_kernel() {
    if (threadIdx.x < NE) g_cnt[threadIdx.x] = 0;
}

// which=0: src = xin (input x), dst = g_h ; which=1: src = g_x2, dst = g_h2
__global__ void __launch_bounds__(256) rmsnorm_kernel(const float* __restrict__ xin,
                                                      const float* __restrict__ w, int which) {
    const float* src = which ? g_x2 : xin;
    float* dst = which ? g_h2 : g_h;
    int t = blockIdx.x;
    const float* xr = src + (size_t)t * DIM;
    float s = 0.f;
    for (int i = threadIdx.x; i < DIM; i += 256) { float v = xr[i]; s += v * v; }
    __shared__ float red[8];
    for (int o = 16; o; o >>= 1) s += __shfl_xor_sync(0xffffffffu, s, o);
    if ((threadIdx.x & 31) == 0) red[threadIdx.x >> 5] = s;
    __syncthreads();
    if (threadIdx.x == 0) {
        float v = 0.f;
        #pragma unroll
        for (int i = 0; i < 8; i++) v += red[i];
        red[0] = v;
    }
    __syncthreads();
    float rs = rsqrtf(red[0] * (1.f / DIM) + EPSV);
    float* dr = dst + (size_t)t * DIM;
    for (int i = threadIdx.x; i < DIM; i += 256) dr[i] = xr[i] * rs * w[i];
}

__global__ void __launch_bounds__(256) rope_kernel() {
    int t = blockIdx.x;
    for (int it = threadIdx.x; it < 1024; it += 256) {
        int which = it >> 9;          // 0 = q, 1 = k
        int rem = it & 511;
        int hh = rem >> 5, j = rem & 31;
        float inv = expf(-0.28782313662425575f * (float)j);  // 10000^(-j/32)
        float ang = (float)t * inv;
        float sn, cs;
        sincosf(ang, &sn, &cs);
        float* p = g_qkv + (size_t)t * 3072 + which * 1024 + hh * 64;
        float x1 = p[j], x2 = p[j + 32];
        p[j]      = x1 * cs - x2 * sn;
        p[j + 32] = x2 * cs + x1 * sn;
    }
}

// ------------------------- shared NT-GEMM core (64x64 tile, BK=16, 4x4 micro) ----
// C-tile = A[rows m0..m0+63 (opt. gathered, valid < Mv)] * B[n0..n0+63]^T
// A row-major (lda=K), B row-major (ldb=K). Caller passes Bt = B + n0*K.
__device__ __forceinline__ void gemm64(const float* __restrict__ A,
                                       const float* __restrict__ Bt, int K,
                                       int m0, int Mv, const int* __restrict__ gidx,
                                       float acc[4][4]) {
    __shared__ float As[16][65];
    __shared__ float Bs[16][65];
    int tid = threadIdx.x;
    int tx = tid & 15, ty = tid >> 4;
    int lr = tid >> 2;      // 0..63 tile row
    int kq = tid & 3;       // float4 index in k
    const float* arow = A;
    bool valid = (m0 + lr) < Mv;
    if (valid) {
        int row = gidx ? gidx[m0 + lr] : (m0 + lr);
        arow = A + (size_t)row * K;
    }
    const float* brow = Bt + (size_t)lr * K;
    for (int k0 = 0; k0 < K; k0 += 16) {
        float4 av = valid ? *(const float4*)(arow + k0 + 4 * kq)
                          : make_float4(0.f, 0.f, 0.f, 0.f);
        float4 bv = *(const float4*)(brow + k0 + 4 * kq);
        __syncthreads();
        As[4 * kq + 0][lr] = av.x; As[4 * kq + 1][lr] = av.y;
        As[4 * kq + 2][lr] = av.z; As[4 * kq + 3][lr] = av.w;
        Bs[4 * kq + 0][lr] = bv.x; Bs[4 * kq + 1][lr] = bv.y;
        Bs[4 * kq + 2][lr] = bv.z; Bs[4 * kq + 3][lr] = bv.w;
        __syncthreads();
        #pragma unroll
        for (int k = 0; k < 16; k++) {
            float a[4], b[4];
            #pragma unroll
            for (int i = 0; i < 4; i++) a[i] = As[k][4 * ty + i];
            #pragma unroll
            for (int j = 0; j < 4; j++) b[j] = Bs[k][4 * tx + j];
            #pragma unroll
            for (int i = 0; i < 4; i++)
                #pragma unroll
                for (int j = 0; j < 4; j++) acc[i][j] = fmaf(a[i], b[j], acc[i][j]);
        }
    }
}

// ------------------------- GEMM wrappers -------------------------
__global__ void __launch_bounds__(256) gemm_qkv_kernel(const float* __restrict__ Bw) {
    int m0 = blockIdx.x * 64, n0 = blockIdx.y * 64;
    float acc[4][4];
    #pragma unroll
    for (int i = 0; i < 4; i++)
        #pragma unroll
        for (int j = 0; j < 4; j++) acc[i][j] = 0.f;
    gemm64(g_h, Bw + (size_t)n0 * DIM, DIM, m0, SQ, nullptr, acc);
    int tx = threadIdx.x & 15, ty = threadIdx.x >> 4;
    #pragma unroll
    for (int i = 0; i < 4; i++)
        #pragma unroll
        for (int j = 0; j < 4; j++)
            g_qkv[(size_t)(m0 + 4 * ty + i) * (3 * DIM) + n0 + 4 * tx + j] = acc[i][j];
}

__global__ void __launch_bounds__(256) gemm_out_kernel(const float* __restrict__ Bw,
                                                       const float* __restrict__ xres) {
    int m0 = blockIdx.x * 64, n0 = blockIdx.y * 64;
    float acc[4][4];
    #pragma unroll
    for (int i = 0; i < 4; i++)
        #pragma unroll
        for (int j = 0; j < 4; j++) acc[i][j] = 0.f;
    gemm64(g_o, Bw + (size_t)n0 * DIM, DIM, m0, SQ, nullptr, acc);
    int tx = threadIdx.x & 15, ty = threadIdx.x >> 4;
    #pragma unroll
    for (int i = 0; i < 4; i++)
        #pragma unroll
        for (int j = 0; j < 4; j++) {
            size_t off = (size_t)(m0 + 4 * ty + i) * DIM + n0 + 4 * tx + j;
            g_x2[off] = xres[off] + acc[i][j];
        }
}

__global__ void __launch_bounds__(256) gemm_moe1_kernel(const float* __restrict__ w1) {
    int e = blockIdx.z;
    int Mv = g_cnt[e];
    int m0 = blockIdx.x * 64;
    if (m0 >= Mv) return;
    int n0 = blockIdx.y * 64;
    float acc[4][4];
    #pragma unroll
    for (int i = 0; i < 4; i++)
        #pragma unroll
        for (int j = 0; j < 4; j++) acc[i][j] = 0.f;
    gemm64(g_h2, w1 + (size_t)e * DFF * DIM + (size_t)n0 * DIM, DIM,
           m0, Mv, g_atok + (size_t)e * SQ, acc);
    int tx = threadIdx.x & 15, ty = threadIdx.x >> 4;
    #pragma unroll
    for (int i = 0; i < 4; i++) {
        int r = m0 + 4 * ty + i;
        if (r < Mv) {
            #pragma unroll
            for (int j = 0; j < 4; j++) {
                float v = acc[i][j];
                float g = 0.5f * v * (1.f + erff(v * 0.7071067811865476f));
                g_hid[((size_t)e * SQ + r) * DFF + n0 + 4 * tx + j] = g;
            }
        }
    }
}

__global__ void __launch_bounds__(256) gemm_moe2_kernel(const float* __restrict__ w2) {
    int e = blockIdx.z;
    int Mv = g_cnt[e];
    int m0 = blockIdx.x * 64;
    if (m0 >= Mv) return;
    int n0 = blockIdx.y * 64;
    float acc[4][4];
    #pragma unroll
    for (int i = 0; i < 4; i++)
        #pragma unroll
        for (int j = 0; j < 4; j++) acc[i][j] = 0.f;
    gemm64(g_hid + (size_t)e * SQ * DFF, w2 + (size_t)e * DIM * DFF + (size_t)n0 * DFF,
           DFF, m0, Mv, nullptr, acc);
    int tx = threadIdx.x & 15, ty = threadIdx.x >> 4;
    #pragma unroll
    for (int i = 0; i < 4; i++) {
        int r = m0 + 4 * ty + i;
        if (r < Mv) {
            int tok  = g_atok [(size_t)e * SQ + r];
            int slot = g_aslot[(size_t)e * SQ + r];
            float wt = g_topw[tok * 2 + slot];
            #pragma unroll
            for (int j = 0; j < 4; j++)
                g_y[((size_t)tok * 2 + slot) * DIM + n0 + 4 * tx + j] = acc[i][j] * wt;
        }
    }
}

// ------------------------- attention (flash, fp32) -------------------------
// grid (32 q-tiles, 16 heads), 256 threads, dyn smem 49664 B
__global__ void __launch_bounds__(256) attn_kernel() {
    extern __shared__ float sm[];
    float* Qs = sm;              // [64][65]  [r][d], pre-scaled by 1/8
    float* KP = sm + 64 * 65;    // [64][65]  K as [c][d], then reused for P [r][c]
    float* Vs = KP + 64 * 65;    // [64][64]  [c][d]
    int h  = blockIdx.y;
    int q0 = blockIdx.x * 64;
    int tid = threadIdx.x, tx = tid & 15, ty = tid >> 4;

    for (int idx = tid; idx < 64 * 16; idx += 256) {
        int r = idx >> 4, d4 = idx & 15;
        float4 v = *(const float4*)(g_qkv + (size_t)(q0 + r) * 3072 + h * 64 + d4 * 4);
        float* q = Qs + r * 65 + d4 * 4;
        q[0] = v.x * 0.125f; q[1] = v.y * 0.125f; q[2] = v.z * 0.125f; q[3] = v.w * 0.125f;
    }

    float m[4], l[4], O[4][4];
    #pragma unroll
    for (int i = 0; i < 4; i++) {
        m[i] = NEG_INF; l[i] = 0.f;
        #pragma unroll
        for (int j = 0; j < 4; j++) O[i][j] = 0.f;
    }

    int nk = blockIdx.x;
    for (int kt = 0; kt <= nk; kt++) {
        int k0 = kt * 64;
        __syncthreads();   // prior iteration done with KP/Vs
        for (int idx = tid; idx < 64 * 16; idx += 256) {
            int r = idx >> 4, d4 = idx & 15;
            const float* kb = g_qkv + (size_t)(k0 + r) * 3072 + 1024 + h * 64 + d4 * 4;
            float4 kv = *(const float4*)kb;
            float* kp = KP + r * 65 + d4 * 4;
            kp[0] = kv.x; kp[1] = kv.y; kp[2] = kv.z; kp[3] = kv.w;
            float4 vv = *(const float4*)(kb + 1024);
            *(float4*)(Vs + r * 64 + d4 * 4) = vv;
        }
        __syncthreads();

        float sacc[4][4];
        #pragma unroll
        for (int i = 0; i < 4; i++)
            #pragma unroll
            for (int j = 0; j < 4; j++) sacc[i][j] = 0.f;
        for (int d = 0; d < 64; d++) {
            float a[4], b[4];
            #pragma unroll
            for (int i = 0; i < 4; i++) a[i] = Qs[(4 * ty + i) * 65 + d];
            #pragma unroll
            for (int j = 0; j < 4; j++) b[j] = KP[(4 * tx + j) * 65 + d];
            #pragma unroll
            for (int i = 0; i < 4; i++)
                #pragma unroll
                for (int j = 0; j < 4; j++) sacc[i][j] = fmaf(a[i], b[j], sacc[i][j]);
        }
        if (kt == nk) {  // diagonal tile: mask key col > query row
            #pragma unroll
            for (int i = 0; i < 4; i++)
                #pragma unroll
                for (int j = 0; j < 4; j++)
                    if (4 * tx + j > 4 * ty + i) sacc[i][j] = NEG_INF;
        }

        float pl[4][4];
        #pragma unroll
        for (int i = 0; i < 4; i++) {
            float mm = sacc[i][0];
            #pragma unroll
            for (int j = 1; j < 4; j++) mm = fmaxf(mm, sacc[i][j]);
            #pragma unroll
            for (int o = 8; o; o >>= 1) mm = fmaxf(mm, __shfl_xor_sync(0xffffffffu, mm, o));
            float mn = fmaxf(m[i], mm);
            float alpha = expf(m[i] - mn);
            float sum = 0.f;
            #pragma unroll
            for (int j = 0; j < 4; j++) {
                float p = expf(sacc[i][j] - mn);
                pl[i][j] = p; sum += p;
            }
            #pragma unroll
            for (int o = 8; o; o >>= 1) sum += __shfl_xor_sync(0xffffffffu, sum, o);
            l[i] = l[i] * alpha + sum;
            #pragma unroll
            for (int j = 0; j < 4; j++) O[i][j] *= alpha;
            m[i] = mn;
        }

        __syncthreads();  // all S-reads of K done; reuse KP for P
        #pragma unroll
        for (int i = 0; i < 4; i++)
            #pragma unroll
            for (int j = 0; j < 4; j++)
                KP[(4 * ty + i) * 65 + 4 * tx + j] = pl[i][j];
        __syncthreads();

        for (int c = 0; c < 64; c++) {
            float a[4], b[4];
            #pragma unroll
            for (int i = 0; i < 4; i++) a[i] = KP[(4 * ty + i) * 65 + c];
            #pragma unroll
            for (int j = 0; j < 4; j++) b[j] = Vs[c * 64 + 4 * tx + j];
            #pragma unroll
            for (int i = 0; i < 4; i++)
                #pragma unroll
                for (int j = 0; j < 4; j++) O[i][j] = fmaf(a[i], b[j], O[i][j]);
        }
    }

    #pragma unroll
    for (int i = 0; i < 4; i++) {
        float inv = 1.f / l[i];
        #pragma unroll
        for (int j = 0; j < 4; j++)
            g_o[(size_t)(q0 + 4 * ty + i) * DIM + h * 64 + 4 * tx + j] = O[i][j] * inv;
    }
}

// ------------------------- router / aux / combine -------------------------
__global__ void __launch_bounds__(256) router_kernel(const float* __restrict__ rw) {
    int t = blockIdx.x;
    int wid = threadIdx.x >> 5, lane = threadIdx.x & 31;
    const float* hr = g_h2 + (size_t)t * DIM;
    const float* wr = rw + (size_t)wid * DIM;
    float s = 0.f;
    for (int i = lane; i < DIM; i += 32) s += hr[i] * wr[i];
    for (int o = 16; o; o >>= 1) s += __shfl_xor_sync(0xffffffffu, s, o);
    __shared__ float lg[NE];
    if (lane == 0) lg[wid] = s;
    __syncthreads();
    if (threadIdx.x == 0) {
        float mx = lg[0];
        #pragma unroll
        for (int e = 1; e < NE; e++) mx = fmaxf(mx, lg[e]);
        float p[NE]; float se = 0.f;
        #pragma unroll
        for (int e = 0; e < NE; e++) { p[e] = expf(lg[e] - mx); se += p[e]; }
        float inv = 1.f / se;
        #pragma unroll
        for (int e = 0; e < NE; e++) { p[e] *= inv; g_probs[t * NE + e] = p[e]; }
        int i0 = 0;
        #pragma unroll
        for (int e = 1; e < NE; e++) if (p[e] > p[i0]) i0 = e;
        int i1 = (i0 == 0) ? 1 : 0;
        #pragma unroll
        for (int e = 0; e < NE; e++) if (e != i0 && p[e] > p[i1]) i1 = e;
        float sw = p[i0] + p[i1];
        g_topw[t * 2 + 0] = p[i0] / sw;
        g_topw[t * 2 + 1] = p[i1] / sw;
        int pos0 = atomicAdd(&g_cnt[i0], 1);
        g_atok[(size_t)i0 * SQ + pos0] = t; g_aslot[(size_t)i0 * SQ + pos0] = 0;
        int pos1 = atomicAdd(&g_cnt[i1], 1);
        g_atok[(size_t)i1 * SQ + pos1] = t; g_aslot[(size_t)i1 * SQ + pos1] = 1;
    }
}

__global__ void __launch_bounds__(256) aux_kernel(float* __restrict__ out, int do_write) {
    int wid = threadIdx.x >> 5, lane = threadIdx.x & 31;
    float s = 0.f;
    for (int t = lane; t < SQ; t += 32) s += g_probs[t * NE + wid];
    for (int o = 16; o; o >>= 1) s += __shfl_xor_sync(0xffffffffu, s, o);
    __shared__ float mp[NE];
    if (lane == 0) mp[wid] = s * (1.f / SQ);
    __syncthreads();
    if (threadIdx.x == 0 && do_write) {
        float a = 0.f;
        #pragma unroll
        for (int e = 0; e < NE; e++) a += mp[e] * mp[e];
        out[(size_t)SQ * DIM] = (float)NE * a;
    }
}

__global__ void __launch_bounds__(256) combine_kernel(float* __restrict__ out) {
    int t = blockIdx.x;
    for (int i = threadIdx.x; i < DIM; i += 256) {
        size_t off = (size_t)t * DIM + i;
        out[off] = g_x2[off] + g_y[((size_t)t * 2) * DIM + i]
                            + g_y[((size_t)t * 2 + 1) * DIM + i];
    }
}

// ------------------------- launch -------------------------
extern "C" void kernel_launch(void* const* d_in, const int* in_sizes, int n_in,
                              void* d_out, int out_size) {
    const float* x        = (const float*)d_in[0];
    const float* qkv_w    = (const float*)d_in[1];
    const float* out_w    = (const float*)d_in[2];
    const float* router_w = (const float*)d_in[3];
    const float* w1       = (const float*)d_in[4];
    const float* w2       = (const float*)d_in[5];
    const float* n1       = (const float*)d_in[6];
    const float* n2       = (const float*)d_in[7];
    float* out = (float*)d_out;

    cudaFuncSetAttribute(attn_kernel, cudaFuncAttributeMaxDynamicSharedMemorySize, 49664);

    zero_cnt_kernel<<<1, 32>>>();
    rmsnorm_kernel<<<SQ, 256>>>(x, n1, 0);
    gemm_qkv_kernel<<<dim3(SQ / 64, 3 * DIM / 64), 256>>>(qkv_w);
    rope_kernel<<<SQ, 256>>>();
    attn_kernel<<<dim3(SQ / 64, NH), 256, 49664>>>();
    gemm_out_kernel<<<dim3(SQ / 64, DIM / 64), 256>>>(out_w, x);
    rmsnorm_kernel<<<SQ, 256>>>(x, n2, 1);
    router_kernel<<<SQ, 256>>>(router_w);
    aux_kernel<<<1, 256>>>(out, out_size > SQ * DIM ? 1 : 0);
    gemm_moe1_kernel<<<dim3(SQ / 64, DFF / 64, NE), 256>>>(w1);
    gemm_moe2_kernel<<<dim3(SQ / 64, DIM / 64, NE), 256>>>(w2);
    combine_kernel<<<SQ, 256>>>(out);
}

// round 5
// speedup vs baseline: 2.2513x; 2.2513x over previous
#include <cuda_runtime.h>
#include <math.h>
#include <stdint.h>

#define SQ   2048
#define DIM  1024
#define NH   16
#define HD   64
#define DFF  4096
#define NE   8
#define EPSV 1.1920928955078125e-07f
#define NEG_INF (__int_as_float(0xff800000))

// ------------------------- scratch (device globals) -------------------------
__device__ float g_h   [(size_t)SQ*DIM];
__device__ float g_qkv [(size_t)SQ*3*DIM];
__device__ float g_o   [(size_t)SQ*DIM];
__device__ float g_x2  [(size_t)SQ*DIM];
__device__ float g_h2  [(size_t)SQ*DIM];
__device__ float g_probs[(size_t)SQ*NE];
__device__ float g_topw [(size_t)SQ*2];
__device__ int   g_cnt  [NE];
__device__ int   g_atok [(size_t)NE*SQ];
__device__ int   g_aslot[(size_t)NE*SQ];
__device__ float g_hid  [(size_t)NE*SQ*DFF];   // 256 MB bss scratch
__device__ float g_y    [(size_t)SQ*2*DIM];

// ------------------------- helpers -------------------------
__device__ __forceinline__ uint32_t f2tf32(float x) {
    uint32_t r;
    asm("cvt.rna.tf32.f32 %0, %1;" : "=r"(r) : "f"(x));
    return r;
}

// float4 accumulator, scalar operands — nothing address-taken, no local memory.
__device__ __forceinline__ void mma4(float4& c,
                                     uint32_t a0, uint32_t a1, uint32_t a2, uint32_t a3,
                                     uint32_t b0, uint32_t b1) {
    asm volatile(
        "mma.sync.aligned.m16n8k8.row.col.f32.tf32.tf32.f32 "
        "{%0,%1,%2,%3}, {%4,%5,%6,%7}, {%8,%9}, {%0,%1,%2,%3};"
        : "+f"(c.x), "+f"(c.y), "+f"(c.z), "+f"(c.w)
        : "r"(a0), "r"(a1), "r"(a2), "r"(a3), "r"(b0), "r"(b1));
}

__device__ __forceinline__ void cp_async16(uint32_t saddr, const void* gptr, int srcsz) {
    asm volatile("cp.async.ca.shared.global [%0], [%1], 16, %2;"
                 :: "r"(saddr), "l"(gptr), "r"(srcsz) : "memory");
}
__device__ __forceinline__ void cp_commit() { asm volatile("cp.async.commit_group;" ::: "memory"); }
__device__ __forceinline__ void cp_wait0()  { asm volatile("cp.async.wait_group 0;" ::: "memory"); }

// ------------------------- small kernels -------------------------
__global__ void zero_cnt_kernel() {
    if (threadIdx.x < NE) g_cnt[threadIdx.x] = 0;
}

__global__ void __launch_bounds__(256) rmsnorm_kernel(const float* __restrict__ xin,
                                                      const float* __restrict__ w, int which) {
    const float* src = which ? g_x2 : xin;
    float* dst = which ? g_h2 : g_h;
    int t = blockIdx.x;
    const float* xr = src + (size_t)t * DIM;
    float s = 0.f;
    for (int i = threadIdx.x; i < DIM; i += 256) { float v = xr[i]; s += v * v; }
    __shared__ float red[8];
    for (int o = 16; o; o >>= 1) s += __shfl_xor_sync(0xffffffffu, s, o);
    if ((threadIdx.x & 31) == 0) red[threadIdx.x >> 5] = s;
    __syncthreads();
    if (threadIdx.x == 0) {
        float v = 0.f;
        #pragma unroll
        for (int i = 0; i < 8; i++) v += red[i];
        red[0] = v;
    }
    __syncthreads();
    float rs = rsqrtf(red[0] * (1.f / DIM) + EPSV);
    float* dr = dst + (size_t)t * DIM;
    for (int i = threadIdx.x; i < DIM; i += 256) dr[i] = xr[i] * rs * w[i];
}

__global__ void __launch_bounds__(256) rope_kernel() {
    int t = blockIdx.x;
    for (int it = threadIdx.x; it < 1024; it += 256) {
        int which = it >> 9;
        int rem = it & 511;
        int hh = rem >> 5, j = rem & 31;
        float inv = expf(-0.28782313662425575f * (float)j);
        float ang = (float)t * inv;
        float sn, cs;
        sincosf(ang, &sn, &cs);
        float* p = g_qkv + (size_t)t * 3072 + which * 1024 + hh * 64;
        float x1 = p[j], x2 = p[j + 32];
        p[j]      = x1 * cs - x2 * sn;
        p[j + 32] = x2 * cs + x1 * sn;
    }
}

// ------------------------- tf32 tensor-core GEMM -------------------------
// C[M,N] = A[M,K]*B[N,K]^T. 128x128 tile, BK=16, 512 threads (4x4 warps, 32x32 warp tile).
// PREC=1: 3xTF32 (hi/lo split) for full-accuracy (QKV / out-proj feed the router decision).
// All accumulators/fragments are named scalars/float4 — zero local memory by construction.
#define BROW 20

#define LOADB(J) \
    float fb##J##0 = bs[(wn * 32 + 8 * J + g) * BROW + kk + t]; \
    float fb##J##1 = bs[(wn * 32 + 8 * J + g) * BROW + kk + t + 4];

#define CVTB(J) \
    uint32_t hb##J##0 = f2tf32(fb##J##0); \
    uint32_t hb##J##1 = f2tf32(fb##J##1);

#define SPLB(J) \
    uint32_t hb##J##0 = f2tf32(fb##J##0); \
    uint32_t lb##J##0 = f2tf32(fb##J##0 - __uint_as_float(hb##J##0)); \
    uint32_t hb##J##1 = f2tf32(fb##J##1); \
    uint32_t lb##J##1 = f2tf32(fb##J##1 - __uint_as_float(hb##J##1));

#define DOROW(TI) { \
    int rb = (wm * 32 + TI * 16 + g) * BROW + kk + t; \
    uint32_t ha0 = f2tf32(as[rb]); \
    uint32_t ha1 = f2tf32(as[rb + 8 * BROW]); \
    uint32_t ha2 = f2tf32(as[rb + 4]); \
    uint32_t ha3 = f2tf32(as[rb + 8 * BROW + 4]); \
    mma4(c##TI##0, ha0, ha1, ha2, ha3, hb00, hb01); \
    mma4(c##TI##1, ha0, ha1, ha2, ha3, hb10, hb11); \
    mma4(c##TI##2, ha0, ha1, ha2, ha3, hb20, hb21); \
    mma4(c##TI##3, ha0, ha1, ha2, ha3, hb30, hb31); }

#define DOROW_P(TI) { \
    int rb = (wm * 32 + TI * 16 + g) * BROW + kk + t; \
    float fa0 = as[rb]; \
    float fa1 = as[rb + 8 * BROW]; \
    float fa2 = as[rb + 4]; \
    float fa3 = as[rb + 8 * BROW + 4]; \
    uint32_t ha0 = f2tf32(fa0), ha1 = f2tf32(fa1), ha2 = f2tf32(fa2), ha3 = f2tf32(fa3); \
    uint32_t la0 = f2tf32(fa0 - __uint_as_float(ha0)); \
    uint32_t la1 = f2tf32(fa1 - __uint_as_float(ha1)); \
    uint32_t la2 = f2tf32(fa2 - __uint_as_float(ha2)); \
    uint32_t la3 = f2tf32(fa3 - __uint_as_float(ha3)); \
    mma4(c##TI##0, la0, la1, la2, la3, hb00, hb01); \
    mma4(c##TI##0, ha0, ha1, ha2, ha3, lb00, lb01); \
    mma4(c##TI##0, ha0, ha1, ha2, ha3, hb00, hb01); \
    mma4(c##TI##1, la0, la1, la2, la3, hb10, hb11); \
    mma4(c##TI##1, ha0, ha1, ha2, ha3, lb10, lb11); \
    mma4(c##TI##1, ha0, ha1, ha2, ha3, hb10, hb11); \
    mma4(c##TI##2, la0, la1, la2, la3, hb20, hb21); \
    mma4(c##TI##2, ha0, ha1, ha2, ha3, lb20, lb21); \
    mma4(c##TI##2, ha0, ha1, ha2, ha3, hb20, hb21); \
    mma4(c##TI##3, la0, la1, la2, la3, hb30, hb31); \
    mma4(c##TI##3, ha0, ha1, ha2, ha3, lb30, lb31); \
    mma4(c##TI##3, ha0, ha1, ha2, ha3, hb30, hb31); }

#define EPI1(CT, J) do { \
    int col = n0 + wn * 32 + 8 * J + 2 * t; \
    float v0 = rh ? (CT).z : (CT).x; \
    float v1 = rh ? (CT).w : (CT).y; \
    if (MODE == 0) { \
        *(float2*)(g_qkv + (size_t)r * 3072 + col) = make_float2(v0, v1); \
    } else if (MODE == 1) { \
        size_t off = (size_t)r * DIM + col; \
        g_x2[off]     = xres[off]     + v0; \
        g_x2[off + 1] = xres[off + 1] + v1; \
    } else if (MODE == 2) { \
        float gl0 = 0.5f * v0 * (1.f + erff(v0 * 0.7071067811865476f)); \
        float gl1 = 0.5f * v1 * (1.f + erff(v1 * 0.7071067811865476f)); \
        *(float2*)(g_hid + (size_t)e * SQ * DFF + (size_t)r * DFF + col) = make_float2(gl0, gl1); \
    } else { \
        *(float2*)(g_y + ((size_t)tok * 2 + slot) * DIM + col) = make_float2(v0 * wt, v1 * wt); \
    } \
} while (0)

template<int MODE, int PREC>
__global__ void __launch_bounds__(512) tc_gemm(const float* __restrict__ W,
                                               const float* __restrict__ xres,
                                               int Kdim) {
    __shared__ float As[2][128 * BROW];
    __shared__ float Bs[2][128 * BROW];

    int m0 = blockIdx.x * 128, n0 = blockIdx.y * 128;
    int e = (MODE >= 2) ? blockIdx.z : 0;
    int Mv = (MODE >= 2) ? g_cnt[e] : SQ;
    if (MODE >= 2 && m0 >= Mv) return;

    const float* A;
    const float* B;
    if (MODE == 0)      { A = g_h;                          B = W; }
    else if (MODE == 1) { A = g_o;                          B = W; }
    else if (MODE == 2) { A = g_h2;                         B = W + (size_t)e * DFF * DIM; }
    else                { A = g_hid + (size_t)e * SQ * DFF; B = W + (size_t)e * DIM * DFF; }

    int tid = threadIdx.x;
    int lr = tid >> 2, kq = tid & 3;

    const float* arow;
    int apred = 16;
    if (MODE == 2) {
        int r = m0 + lr;
        bool valid = r < Mv;
        apred = valid ? 16 : 0;
        int row = valid ? g_atok[(size_t)e * SQ + r] : 0;
        arow = A + (size_t)row * Kdim + kq * 4;
    } else {
        arow = A + (size_t)(m0 + lr) * Kdim + kq * 4;
    }
    const float* brow = B + (size_t)(n0 + lr) * Kdim + kq * 4;

    uint32_t a_s = (uint32_t)__cvta_generic_to_shared(&As[0][lr * BROW + kq * 4]);
    uint32_t b_s = (uint32_t)__cvta_generic_to_shared(&Bs[0][lr * BROW + kq * 4]);
    const uint32_t bufoff = 128 * BROW * 4;

#define LOADG(BUF, K0)                                            \
    do {                                                          \
        cp_async16(a_s + (BUF) * bufoff, arow + (K0), apred);     \
        cp_async16(b_s + (BUF) * bufoff, brow + (K0), 16);        \
        cp_commit();                                              \
    } while (0)

    int warp = tid >> 5, lane = tid & 31;
    int wm = warp >> 2, wn = warp & 3;
    int g = lane >> 2, t = lane & 3;

    float4 c00 = make_float4(0.f, 0.f, 0.f, 0.f);
    float4 c01 = c00, c02 = c00, c03 = c00;
    float4 c10 = c00, c11 = c00, c12 = c00, c13 = c00;

    int nIter = Kdim >> 4;
    LOADG(0, 0);

    for (int it = 0; it < nIter; ++it) {
        cp_wait0();
        __syncthreads();
        int nxt = it + 1;
        if (nxt < nIter) LOADG(nxt & 1, nxt << 4);

        const float* as = As[it & 1];
        const float* bs = Bs[it & 1];
        #pragma unroll
        for (int kh = 0; kh < 2; kh++) {
            int kk = kh * 8;
            LOADB(0) LOADB(1) LOADB(2) LOADB(3)
            if (PREC) {
                SPLB(0) SPLB(1) SPLB(2) SPLB(3)
                DOROW_P(0)
                DOROW_P(1)
            } else {
                CVTB(0) CVTB(1) CVTB(2) CVTB(3)
                DOROW(0)
                DOROW(1)
            }
        }
        __syncthreads();
    }

    // ---------------- epilogue ----------------
    for (int rh = 0; rh < 2; rh++) {
        {
            int r = m0 + wm * 32 + g + rh * 8;
            if (!(MODE >= 2 && r >= Mv)) {
                int tok = 0, slot = 0; float wt = 0.f;
                if (MODE == 3) {
                    tok  = g_atok [(size_t)e * SQ + r];
                    slot = g_aslot[(size_t)e * SQ + r];
                    wt   = g_topw[tok * 2 + slot];
                }
                EPI1(c00, 0); EPI1(c01, 1); EPI1(c02, 2); EPI1(c03, 3);
            }
        }
        {
            int r = m0 + wm * 32 + 16 + g + rh * 8;
            if (!(MODE >= 2 && r >= Mv)) {
                int tok = 0, slot = 0; float wt = 0.f;
                if (MODE == 3) {
                    tok  = g_atok [(size_t)e * SQ + r];
                    slot = g_aslot[(size_t)e * SQ + r];
                    wt   = g_topw[tok * 2 + slot];
                }
                EPI1(c10, 0); EPI1(c11, 1); EPI1(c12, 2); EPI1(c13, 3);
            }
        }
    }
#undef LOADG
}

// ------------------------- attention (flash, fp32) -------------------------
__global__ void __launch_bounds__(256) attn_kernel() {
    extern __shared__ float sm[];
    float* Qs = sm;              // [64][65]
    float* KP = sm + 64 * 65;    // [64][65]
    float* Vs = KP + 64 * 65;    // [64][64]
    int h  = blockIdx.y;
    int q0 = blockIdx.x * 64;
    int tid = threadIdx.x, tx = tid & 15, ty = tid >> 4;

    for (int idx = tid; idx < 64 * 16; idx += 256) {
        int r = idx >> 4, d4 = idx & 15;
        float4 v = *(const float4*)(g_qkv + (size_t)(q0 + r) * 3072 + h * 64 + d4 * 4);
        float* q = Qs + r * 65 + d4 * 4;
        q[0] = v.x * 0.125f; q[1] = v.y * 0.125f; q[2] = v.z * 0.125f; q[3] = v.w * 0.125f;
    }

    float m[4], l[4], O[4][4];
    #pragma unroll
    for (int i = 0; i < 4; i++) {
        m[i] = NEG_INF; l[i] = 0.f;
        #pragma unroll
        for (int j = 0; j < 4; j++) O[i][j] = 0.f;
    }

    int nk = blockIdx.x;
    for (int kt = 0; kt <= nk; kt++) {
        int k0 = kt * 64;
        __syncthreads();
        for (int idx = tid; idx < 64 * 16; idx += 256) {
            int r = idx >> 4, d4 = idx & 15;
            const float* kb = g_qkv + (size_t)(k0 + r) * 3072 + 1024 + h * 64 + d4 * 4;
            float4 kv = *(const float4*)kb;
            float* kp = KP + r * 65 + d4 * 4;
            kp[0] = kv.x; kp[1] = kv.y; kp[2] = kv.z; kp[3] = kv.w;
            float4 vv = *(const float4*)(kb + 1024);
            *(float4*)(Vs + r * 64 + d4 * 4) = vv;
        }
        __syncthreads();

        float sacc[4][4];
        #pragma unroll
        for (int i = 0; i < 4; i++)
            #pragma unroll
            for (int j = 0; j < 4; j++) sacc[i][j] = 0.f;
        for (int d = 0; d < 64; d++) {
            float a[4], b[4];
            #pragma unroll
            for (int i = 0; i < 4; i++) a[i] = Qs[(4 * ty + i) * 65 + d];
            #pragma unroll
            for (int j = 0; j < 4; j++) b[j] = KP[(4 * tx + j) * 65 + d];
            #pragma unroll
            for (int i = 0; i < 4; i++)
                #pragma unroll
                for (int j = 0; j < 4; j++) sacc[i][j] = fmaf(a[i], b[j], sacc[i][j]);
        }
        if (kt == nk) {
            #pragma unroll
            for (int i = 0; i < 4; i++)
                #pragma unroll
                for (int j = 0; j < 4; j++)
                    if (4 * tx + j > 4 * ty + i) sacc[i][j] = NEG_INF;
        }

        float pl[4][4];
        #pragma unroll
        for (int i = 0; i < 4; i++) {
            float mm = sacc[i][0];
            #pragma unroll
            for (int j = 1; j < 4; j++) mm = fmaxf(mm, sacc[i][j]);
            #pragma unroll
            for (int o = 8; o; o >>= 1) mm = fmaxf(mm, __shfl_xor_sync(0xffffffffu, mm, o));
            float mn = fmaxf(m[i], mm);
            float alpha = expf(m[i] - mn);
            float sum = 0.f;
            #pragma unroll
            for (int j = 0; j < 4; j++) {
                float p = expf(sacc[i][j] - mn);
                pl[i][j] = p; sum += p;
            }
            #pragma unroll
            for (int o = 8; o; o >>= 1) sum += __shfl_xor_sync(0xffffffffu, sum, o);
            l[i] = l[i] * alpha + sum;
            #pragma unroll
            for (int j = 0; j < 4; j++) O[i][j] *= alpha;
            m[i] = mn;
        }

        __syncthreads();
        #pragma unroll
        for (int i = 0; i < 4; i++)
            #pragma unroll
            for (int j = 0; j < 4; j++)
                KP[(4 * ty + i) * 65 + 4 * tx + j] = pl[i][j];
        __syncthreads();

        for (int cc = 0; cc < 64; cc++) {
            float a[4], b[4];
            #pragma unroll
            for (int i = 0; i < 4; i++) a[i] = KP[(4 * ty + i) * 65 + cc];
            #pragma unroll
            for (int j = 0; j < 4; j++) b[j] = Vs[cc * 64 + 4 * tx + j];
            #pragma unroll
            for (int i = 0; i < 4; i++)
                #pragma unroll
                for (int j = 0; j < 4; j++) O[i][j] = fmaf(a[i], b[j], O[i][j]);
        }
    }

    #pragma unroll
    for (int i = 0; i < 4; i++) {
        float inv = 1.f / l[i];
        #pragma unroll
        for (int j = 0; j < 4; j++)
            g_o[(size_t)(q0 + 4 * ty + i) * DIM + h * 64 + 4 * tx + j] = O[i][j] * inv;
    }
}

// ------------------------- router / aux / combine -------------------------
__global__ void __launch_bounds__(256) router_kernel(const float* __restrict__ rw) {
    int t = blockIdx.x;
    int wid = threadIdx.x >> 5, lane = threadIdx.x & 31;
    const float* hr = g_h2 + (size_t)t * DIM;
    const float* wr = rw + (size_t)wid * DIM;
    float s = 0.f;
    for (int i = lane; i < DIM; i += 32) s += hr[i] * wr[i];
    for (int o = 16; o; o >>= 1) s += __shfl_xor_sync(0xffffffffu, s, o);
    __shared__ float lg[NE];
    if (lane == 0) lg[wid] = s;
    __syncthreads();
    if (threadIdx.x == 0) {
        float mx = lg[0];
        #pragma unroll
        for (int e = 1; e < NE; e++) mx = fmaxf(mx, lg[e]);
        float p[NE]; float se = 0.f;
        #pragma unroll
        for (int e = 0; e < NE; e++) { p[e] = expf(lg[e] - mx); se += p[e]; }
        float inv = 1.f / se;
        #pragma unroll
        for (int e = 0; e < NE; e++) { p[e] *= inv; g_probs[t * NE + e] = p[e]; }
        int i0 = 0;
        #pragma unroll
        for (int e = 1; e < NE; e++) if (p[e] > p[i0]) i0 = e;
        int i1 = (i0 == 0) ? 1 : 0;
        #pragma unroll
        for (int e = 0; e < NE; e++) if (e != i0 && p[e] > p[i1]) i1 = e;
        float sw = p[i0] + p[i1];
        g_topw[t * 2 + 0] = p[i0] / sw;
        g_topw[t * 2 + 1] = p[i1] / sw;
        int pos0 = atomicAdd(&g_cnt[i0], 1);
        g_atok[(size_t)i0 * SQ + pos0] = t; g_aslot[(size_t)i0 * SQ + pos0] = 0;
        int pos1 = atomicAdd(&g_cnt[i1], 1);
        g_atok[(size_t)i1 * SQ + pos1] = t; g_aslot[(size_t)i1 * SQ + pos1] = 1;
    }
}

__global__ void __launch_bounds__(256) aux_kernel(float* __restrict__ out, int do_write) {
    int wid = threadIdx.x >> 5, lane = threadIdx.x & 31;
    float s = 0.f;
    for (int t = lane; t < SQ; t += 32) s += g_probs[t * NE + wid];
    for (int o = 16; o; o >>= 1) s += __shfl_xor_sync(0xffffffffu, s, o);
    __shared__ float mp[NE];
    if (lane == 0) mp[wid] = s * (1.f / SQ);
    __syncthreads();
    if (threadIdx.x == 0 && do_write) {
        float a = 0.f;
        #pragma unroll
        for (int e = 0; e < NE; e++) a += mp[e] * mp[e];
        out[(size_t)SQ * DIM] = (float)NE * a;
    }
}

__global__ void __launch_bounds__(256) combine_kernel(float* __restrict__ out) {
    int t = blockIdx.x;
    for (int i = threadIdx.x; i < DIM; i += 256) {
        size_t off = (size_t)t * DIM + i;
        out[off] = g_x2[off] + g_y[((size_t)t * 2) * DIM + i]
                            + g_y[((size_t)t * 2 + 1) * DIM + i];
    }
}

// ------------------------- launch -------------------------
extern "C" void kernel_launch(void* const* d_in, const int* in_sizes, int n_in,
                              void* d_out, int out_size) {
    const float* x        = (const float*)d_in[0];
    const float* qkv_w    = (const float*)d_in[1];
    const float* out_w    = (const float*)d_in[2];
    const float* router_w = (const float*)d_in[3];
    const float* w1       = (const float*)d_in[4];
    const float* w2       = (const float*)d_in[5];
    const float* n1       = (const float*)d_in[6];
    const float* n2       = (const float*)d_in[7];
    float* out = (float*)d_out;

    cudaFuncSetAttribute(attn_kernel, cudaFuncAttributeMaxDynamicSharedMemorySize, 49664);

    zero_cnt_kernel<<<1, 32>>>();
    rmsnorm_kernel<<<SQ, 256>>>(x, n1, 0);
    tc_gemm<0, 1><<<dim3(SQ / 128, 3 * DIM / 128), 512>>>(qkv_w, nullptr, DIM);
    rope_kernel<<<SQ, 256>>>();
    attn_kernel<<<dim3(SQ / 64, NH), 256, 49664>>>();
    tc_gemm<1, 1><<<dim3(SQ / 128, DIM / 128), 512>>>(out_w, x, DIM);
    rmsnorm_kernel<<<SQ, 256>>>(x, n2, 1);
    router_kernel<<<SQ, 256>>>(router_w);
    aux_kernel<<<1, 256>>>(out, out_size > SQ * DIM ? 1 : 0);
    tc_gemm<2, 0><<<dim3(SQ / 128, DFF / 128, NE), 512>>>(w1, nullptr, DIM);
    tc_gemm<3, 0><<<dim3(SQ / 128, DIM / 128, NE), 512>>>(w2, nullptr, DFF);
    combine_kernel<<<SQ, 256>>>(out);
}